// round 10
// baseline (speedup 1.0000x reference)
#include <cuda_runtime.h>
#include <stddef.h>

#define T_STEPS 200
#define DS 32
#define DA 8
#define HH 128
#define NTHR 512

typedef unsigned long long u64;

// ---- smem layout (float offsets) ----
#define SLOT    16896            // staging slot size (floats)
#define OFF_DEC 33792            // dec [d][k] pad 132  (32*132 = 4224)
#define OFF_HT  38016            // h   [pair][k] f32x2, stride 268 fl (16*268 = 4288)
#define OFF_RH  42304            // r*h same layout (4288)
#define OFF_XT  46592            // gru x [pair][k<40] f32x2, stride 92 (16*92 = 1472)
#define OFF_FB  48064            // flow biases [l*512 + part*128 + n] (1024)
#define OFF_BIH 49088            // 384
#define OFF_BHH 49472            // 384
#define OFF_DB  49856            // 32
#define OFF_TV  49888            // 32
#define OFF_SCR 49920            // split-K partial scratch: 8 * 512 floats (16KB)
#define SMEM_FL 54016            // *4 = 216064 bytes

#define HSTR 268                 // h/rh row stride (floats): 8 pg offsets hit all 32 banks
#define XSTR 92                  // xt row stride

// ---- packed helpers ----
__device__ __forceinline__ u64 pk2(float lo, float hi) {
    u64 r; asm("mov.b64 %0,{%1,%2};" : "=l"(r) : "f"(lo), "f"(hi)); return r;
}
__device__ __forceinline__ void up2(u64 v, float& lo, float& hi) {
    asm("mov.b64 {%0,%1},%2;" : "=f"(lo), "=f"(hi) : "l"(v));
}
__device__ __forceinline__ u64 fma2(u64 a, u64 b, u64 c) {
    u64 d; asm("fma.rn.f32x2 %0,%1,%2,%3;" : "=l"(d) : "l"(a), "l"(b), "l"(c)); return d;
}
__device__ __forceinline__ u64 mul2(u64 a, u64 b) {
    u64 d; asm("mul.rn.f32x2 %0,%1,%2;" : "=l"(d) : "l"(a), "l"(b)); return d;
}
__device__ __forceinline__ u64 add2(u64 a, u64 b) {
    u64 d; asm("add.rn.f32x2 %0,%1,%2;" : "=l"(d) : "l"(a), "l"(b)); return d;
}
__device__ __forceinline__ u64 sub2(u64 a, u64 b) { float x,y,p,q; up2(a,x,y); up2(b,p,q); return pk2(x-p, y-q); }
__device__ __forceinline__ float tanha(float x) {
    float y; asm("tanh.approx.f32 %0,%1;" : "=f"(y) : "f"(x)); return y;
}
__device__ __forceinline__ float siga(float x) { return fmaf(0.5f, tanha(0.5f * x), 0.5f); }
__device__ __forceinline__ u64 tanh2(u64 v) { float a, b; up2(v, a, b); return pk2(tanha(a), tanha(b)); }

// plain (schedulable) 128-bit shared loads: two packed f32x2 values
#define LDX2(x0, x1, ptr) do { \
    const ulonglong2 _v = *reinterpret_cast<const ulonglong2*>(ptr); \
    (x0) = _v.x; (x1) = _v.y; } while (0)

__device__ __forceinline__ void cpa16(float* dst, const float* src) {
    unsigned d = (unsigned)__cvta_generic_to_shared(dst);
    asm volatile("cp.async.cg.shared.global [%0], [%1], 16;" :: "r"(d), "l"(src));
}
#define CP_COMMIT() asm volatile("cp.async.commit_group;" ::: "memory")
#define CP_WAIT0()  asm volatile("cp.async.wait_group 0;" ::: "memory")

// stage matrix for phase ph into slot ph&1
// phases: 0..5 flow (Wr0,Wz0,Wh0,Wr1,Wz1,Wh1) [k][n] contiguous
//         6..8 Whh gates [n][k] pad 132 ; 9 Wih [n][k] pad 44
__device__ __forceinline__ void stage_matrix(int ph, float* sm, int tid,
    const float* fWr, const float* fWz, const float* fWh,
    const float* Whh, const float* Wih)
{
    float* dst = sm + (ph & 1) * SLOT;
    if (ph < 6) {
        const int l = ph / 3, w = ph % 3;
        const float* src = (w == 0 ? fWr : (w == 1 ? fWz : fWh)) + (size_t)l * 129 * 128;
        for (int i = tid; i < 4128; i += NTHR) cpa16(dst + i * 4, src + i * 4);
    } else if (ph < 9) {
        const float* src = Whh + (size_t)(ph - 6) * 128 * 128;
        for (int i = tid; i < 4096; i += NTHR) {
            int r = i >> 5, c = i & 31;
            cpa16(dst + r * 132 + c * 4, src + r * 128 + c * 4);
        }
    } else {
        for (int i = tid; i < 3840; i += NTHR) {
            int r = i / 10, c = i - r * 10;
            cpa16(dst + r * 44 + c * 4, Wih + r * 40 + c * 4);
        }
    }
}

// flow pass, split-K: weights [k][n], 4 cols n0..n0+3; pairs pg, pg+8;
// k range [kbase, kbase+64). acc[4i+c] = (pair_i, col n0+c) partial.
__device__ __forceinline__ void pass_flow_k(const float* sW, const float* xb,
                                            int n0, int kbase, u64 acc[8])
{
#pragma unroll 1
    for (int kk = 0; kk < 64; kk += 4) {
        const int k = kbase + kk;
        const float4 w0 = *(const float4*)&sW[(k+0)*128 + n0];
        const float4 w1 = *(const float4*)&sW[(k+1)*128 + n0];
        const float4 w2 = *(const float4*)&sW[(k+2)*128 + n0];
        const float4 w3 = *(const float4*)&sW[(k+3)*128 + n0];
#pragma unroll
        for (int i = 0; i < 2; i++) {
            u64 x0,x1,x2,x3;
            LDX2(x0,x1, xb + i*(8*HSTR) + k*2);
            LDX2(x2,x3, xb + i*(8*HSTR) + k*2 + 4);
            acc[4*i+0] = fma2(x0, pk2(w0.x,w0.x), acc[4*i+0]);
            acc[4*i+1] = fma2(x0, pk2(w0.y,w0.y), acc[4*i+1]);
            acc[4*i+2] = fma2(x0, pk2(w0.z,w0.z), acc[4*i+2]);
            acc[4*i+3] = fma2(x0, pk2(w0.w,w0.w), acc[4*i+3]);
            acc[4*i+0] = fma2(x1, pk2(w1.x,w1.x), acc[4*i+0]);
            acc[4*i+1] = fma2(x1, pk2(w1.y,w1.y), acc[4*i+1]);
            acc[4*i+2] = fma2(x1, pk2(w1.z,w1.z), acc[4*i+2]);
            acc[4*i+3] = fma2(x1, pk2(w1.w,w1.w), acc[4*i+3]);
            acc[4*i+0] = fma2(x2, pk2(w2.x,w2.x), acc[4*i+0]);
            acc[4*i+1] = fma2(x2, pk2(w2.y,w2.y), acc[4*i+1]);
            acc[4*i+2] = fma2(x2, pk2(w2.z,w2.z), acc[4*i+2]);
            acc[4*i+3] = fma2(x2, pk2(w2.w,w2.w), acc[4*i+3]);
            acc[4*i+0] = fma2(x3, pk2(w3.x,w3.x), acc[4*i+0]);
            acc[4*i+1] = fma2(x3, pk2(w3.y,w3.y), acc[4*i+1]);
            acc[4*i+2] = fma2(x3, pk2(w3.z,w3.z), acc[4*i+2]);
            acc[4*i+3] = fma2(x3, pk2(w3.w,w3.w), acc[4*i+3]);
        }
    }
}

// gh pass (full K, split-N): weights [n][k] pad 132, cols {n0s, n0s+64}; pairs pg, pg+8
__device__ __forceinline__ void pass_gh(const float* sW, const float* xb, int n0s, u64 acc[4])
{
#pragma unroll 2
    for (int k = 0; k < 128; k += 4) {
        const float4 wA = *(const float4*)&sW[n0s*132 + k];
        const float4 wB = *(const float4*)&sW[(n0s+64)*132 + k];
        const u64 a0 = pk2(wA.x,wA.x), a1 = pk2(wA.y,wA.y), a2 = pk2(wA.z,wA.z), a3 = pk2(wA.w,wA.w);
        const u64 b0 = pk2(wB.x,wB.x), b1 = pk2(wB.y,wB.y), b2 = pk2(wB.z,wB.z), b3 = pk2(wB.w,wB.w);
#pragma unroll
        for (int i = 0; i < 2; i++) {
            u64 x0,x1,x2,x3;
            LDX2(x0,x1, xb + i*(8*HSTR) + k*2);
            LDX2(x2,x3, xb + i*(8*HSTR) + k*2 + 4);
            acc[2*i+0] = fma2(x0,a0,acc[2*i+0]); acc[2*i+1] = fma2(x0,b0,acc[2*i+1]);
            acc[2*i+0] = fma2(x1,a1,acc[2*i+0]); acc[2*i+1] = fma2(x1,b1,acc[2*i+1]);
            acc[2*i+0] = fma2(x2,a2,acc[2*i+0]); acc[2*i+1] = fma2(x2,b2,acc[2*i+1]);
            acc[2*i+0] = fma2(x3,a3,acc[2*i+0]); acc[2*i+1] = fma2(x3,b3,acc[2*i+1]);
        }
    }
}

// gi pass (full K=40, split-N): weights [n][k] pad 44, cols {n0s, n0s+64}
__device__ __forceinline__ void pass_gi(const float* sW, const float* xb, int n0s, u64 acc[4])
{
#pragma unroll 2
    for (int k = 0; k < 40; k += 4) {
        const float4 wA = *(const float4*)&sW[n0s*44 + k];
        const float4 wB = *(const float4*)&sW[(n0s+64)*44 + k];
        const u64 a0 = pk2(wA.x,wA.x), a1 = pk2(wA.y,wA.y), a2 = pk2(wA.z,wA.z), a3 = pk2(wA.w,wA.w);
        const u64 b0 = pk2(wB.x,wB.x), b1 = pk2(wB.y,wB.y), b2 = pk2(wB.z,wB.z), b3 = pk2(wB.w,wB.w);
#pragma unroll
        for (int i = 0; i < 2; i++) {
            u64 x0,x1,x2,x3;
            LDX2(x0,x1, xb + i*(8*XSTR) + k*2);
            LDX2(x2,x3, xb + i*(8*XSTR) + k*2 + 4);
            acc[2*i+0] = fma2(x0,a0,acc[2*i+0]); acc[2*i+1] = fma2(x0,b0,acc[2*i+1]);
            acc[2*i+0] = fma2(x1,a1,acc[2*i+0]); acc[2*i+1] = fma2(x1,b1,acc[2*i+1]);
            acc[2*i+0] = fma2(x2,a2,acc[2*i+0]); acc[2*i+1] = fma2(x2,b2,acc[2*i+1]);
            acc[2*i+0] = fma2(x3,a3,acc[2*i+0]); acc[2*i+1] = fma2(x3,b3,acc[2*i+1]);
        }
    }
}

// split-K partial exchange: hi half stores, everyone syncs, lo half folds in
__device__ __forceinline__ void reduce_partials(float* sm, int tid, u64 acc[8])
{
    if (tid >= 256) {
        const int t2 = tid - 256;
#pragma unroll
        for (int q = 0; q < 8; q++)
            *(u64*)&sm[OFF_SCR + q * 512 + t2 * 2] = acc[q];
    }
    __syncthreads();
    if (tid < 256) {
#pragma unroll
        for (int q = 0; q < 8; q++)
            acc[q] = add2(acc[q], *(const u64*)&sm[OFF_SCR + q * 512 + tid * 2]);
    }
}

__global__ void __launch_bounds__(NTHR, 1)
odernn_persistent(const float* __restrict__ s,   const float* __restrict__ a,
                  const float* __restrict__ t,
                  const float* __restrict__ fWr, const float* __restrict__ fbr,
                  const float* __restrict__ fWz, const float* __restrict__ fbz,
                  const float* __restrict__ fWh, const float* __restrict__ fbh,
                  const float* __restrict__ ftw,
                  const float* __restrict__ Wih, const float* __restrict__ Whh,
                  const float* __restrict__ bih, const float* __restrict__ bhh,
                  const float* __restrict__ decW, const float* __restrict__ decb,
                  float* __restrict__ outs, float* __restrict__ hids)
{
    extern __shared__ float sm[];
    const int tid  = threadIdx.x;
    const int row0 = blockIdx.x * 32;

    const int w    = tid >> 5;           // warp 0..15
    const int lane = tid & 31;
    const int wl   = w & 7;              // warp-in-half 0..7
    const int kb   = (w >> 3) * 64;      // split-K base: 0 or 64
    const int pg   = lane >> 2;          // pair-group 0..7 (pairs pg, pg+8)
    const int cg   = lane & 3;           // col-group 0..3
    const int n0c  = wl * 16 + cg * 4;   // flow: 4 consecutive cols
    const int n0s  = w * 4 + cg;         // GRU: cols {n0s, n0s+64}, n0s in 0..63

    const float* htb = sm + OFF_HT + pg * HSTR;
    const float* rhb = sm + OFF_RH + pg * HSTR;
    const float* xtb = sm + OFF_XT + pg * XSTR;

    // ---- one-time init ----
    for (int i = tid; i < 16 * HSTR; i += NTHR) sm[OFF_HT + i] = 0.0f;
    if (tid < 128) {
#pragma unroll
        for (int l = 0; l < 2; l++) {
            sm[OFF_FB + l * 512 +   0 + tid] = fbr[l * HH + tid];
            sm[OFF_FB + l * 512 + 128 + tid] = fbz[l * HH + tid];
            sm[OFF_FB + l * 512 + 256 + tid] = fbh[l * HH + tid];
            sm[OFF_FB + l * 512 + 384 + tid] = ftw[l * HH + tid];
        }
    }
    if (tid < 384) { sm[OFF_BIH + tid] = bih[tid]; sm[OFF_BHH + tid] = bhh[tid]; }
    if (tid < 32) sm[OFF_DB + tid] = decb[tid];
    for (int i = tid; i < 1024; i += NTHR) {       // dec [d][k] pad 132
        int r = i >> 5, c = i & 31;
        cpa16(sm + OFF_DEC + r * 132 + c * 4, decW + r * 128 + c * 4);
    }
    stage_matrix(0, sm, tid, fWr, fWz, fWh, Whh, Wih);
    CP_COMMIT();

#pragma unroll 1
    for (int ti = 0; ti < T_STEPS; ti++) {
        if (tid < 32) sm[OFF_TV + tid] = t[(size_t)(row0 + tid) * T_STEPS + ti];
        for (int i = tid; i < 32 * 40; i += NTHR) {
            const int m = i / 40, c = i - m * 40;
            const size_t row = row0 + m;
            const float v = (c < DS) ? s[(row * T_STEPS + ti) * DS + c]
                                     : a[(row * T_STEPS + ti) * DA + (c - DS)];
            sm[OFF_XT + (m >> 1) * XSTR + 2 * c + (m & 1)] = v;
        }

        u64 zz[8], tvp[2];

        // =================== flow layers ===================
#pragma unroll 1
        for (int l = 0; l < 2; l++) {
            const int phb = l * 3;
            const float* bias = sm + OFF_FB + l * 512;

            // ---- pass r ----
            CP_WAIT0(); __syncthreads();
            stage_matrix(phb + 1, sm, tid, fWr, fWz, fWh, Whh, Wih); CP_COMMIT();
            {
                const float* sW = sm + (phb & 1) * SLOT;
                u64 acc[8];
#pragma unroll
                for (int q = 0; q < 8; q++) acc[q] = 0ULL;
                pass_flow_k(sW, htb, n0c, kb, acc);
                reduce_partials(sm, tid, acc);
                if (tid < 256) {
#pragma unroll
                    for (int i = 0; i < 2; i++) {
                        const int p = pg + 8 * i;
                        tvp[i] = pk2(sm[OFF_TV + 2 * p], sm[OFF_TV + 2 * p + 1]);
                    }
                    const float4 wt = *(const float4*)&sW[128 * 128 + n0c];
                    const float4 br = *(const float4*)&bias[n0c];
#pragma unroll
                    for (int i = 0; i < 2; i++) {
                        const int p = pg + 8 * i;
                        const ulonglong2 hA = *(const ulonglong2*)&sm[OFF_HT + p * HSTR + 2 * n0c];
                        const ulonglong2 hB = *(const ulonglong2*)&sm[OFF_HT + p * HSTR + 2 * n0c + 4];
                        float x, y;
                        ulonglong2 oA, oB;
                        up2(fma2(tvp[i], pk2(wt.x,wt.x), acc[4*i+0]), x, y);
                        oA.x = mul2(pk2(0.8f*siga(x+br.x), 0.8f*siga(y+br.x)), hA.x);
                        up2(fma2(tvp[i], pk2(wt.y,wt.y), acc[4*i+1]), x, y);
                        oA.y = mul2(pk2(0.8f*siga(x+br.y), 0.8f*siga(y+br.y)), hA.y);
                        up2(fma2(tvp[i], pk2(wt.z,wt.z), acc[4*i+2]), x, y);
                        oB.x = mul2(pk2(0.8f*siga(x+br.z), 0.8f*siga(y+br.z)), hB.x);
                        up2(fma2(tvp[i], pk2(wt.w,wt.w), acc[4*i+3]), x, y);
                        oB.y = mul2(pk2(0.8f*siga(x+br.w), 0.8f*siga(y+br.w)), hB.y);
                        *(ulonglong2*)&sm[OFF_RH + p * HSTR + 2 * n0c]     = oA;
                        *(ulonglong2*)&sm[OFF_RH + p * HSTR + 2 * n0c + 4] = oB;
                    }
                }
            }

            // ---- pass z ----
            CP_WAIT0(); __syncthreads();
            stage_matrix(phb + 2, sm, tid, fWr, fWz, fWh, Whh, Wih); CP_COMMIT();
            {
                const float* sW = sm + ((phb + 1) & 1) * SLOT;
                u64 acc[8];
#pragma unroll
                for (int q = 0; q < 8; q++) acc[q] = 0ULL;
                pass_flow_k(sW, htb, n0c, kb, acc);
                reduce_partials(sm, tid, acc);
                if (tid < 256) {
                    const float4 wt = *(const float4*)&sW[128 * 128 + n0c];
                    const float4 bz = *(const float4*)&bias[128 + n0c];
#pragma unroll
                    for (int i = 0; i < 2; i++) {
                        float x, y;
                        up2(fma2(tvp[i], pk2(wt.x,wt.x), acc[4*i+0]), x, y);
                        zz[4*i+0] = pk2(0.4f*siga(x+bz.x), 0.4f*siga(y+bz.x));
                        up2(fma2(tvp[i], pk2(wt.y,wt.y), acc[4*i+1]), x, y);
                        zz[4*i+1] = pk2(0.4f*siga(x+bz.y), 0.4f*siga(y+bz.y));
                        up2(fma2(tvp[i], pk2(wt.z,wt.z), acc[4*i+2]), x, y);
                        zz[4*i+2] = pk2(0.4f*siga(x+bz.z), 0.4f*siga(y+bz.z));
                        up2(fma2(tvp[i], pk2(wt.w,wt.w), acc[4*i+3]), x, y);
                        zz[4*i+3] = pk2(0.4f*siga(x+bz.w), 0.4f*siga(y+bz.w));
                    }
                }
            }

            // ---- pass u + combine ----
            CP_WAIT0(); __syncthreads();
            {
                stage_matrix(phb + 3, sm, tid, fWr, fWz, fWh, Whh, Wih); CP_COMMIT();
                const float* sW = sm + ((phb + 2) & 1) * SLOT;
                u64 acc[8];
#pragma unroll
                for (int q = 0; q < 8; q++) acc[q] = 0ULL;
                pass_flow_k(sW, rhb, n0c, kb, acc);
                reduce_partials(sm, tid, acc);
                if (tid < 256) {
                    const float4 wt = *(const float4*)&sW[128 * 128 + n0c];
                    const float4 bh = *(const float4*)&bias[256 + n0c];
                    const float4 tw = *(const float4*)&bias[384 + n0c];
#pragma unroll
                    for (int i = 0; i < 2; i++) {
                        const int p = pg + 8 * i;
                        const ulonglong2 hA = *(const ulonglong2*)&sm[OFF_HT + p * HSTR + 2 * n0c];
                        const ulonglong2 hB = *(const ulonglong2*)&sm[OFF_HT + p * HSTR + 2 * n0c + 4];
                        const u64 u0 = tanh2(add2(fma2(tvp[i], pk2(wt.x,wt.x), acc[4*i+0]), pk2(bh.x,bh.x)));
                        const u64 u1 = tanh2(add2(fma2(tvp[i], pk2(wt.y,wt.y), acc[4*i+1]), pk2(bh.y,bh.y)));
                        const u64 u2 = tanh2(add2(fma2(tvp[i], pk2(wt.z,wt.z), acc[4*i+2]), pk2(bh.z,bh.z)));
                        const u64 u3 = tanh2(add2(fma2(tvp[i], pk2(wt.w,wt.w), acc[4*i+3]), pk2(bh.w,bh.w)));
                        const u64 f0 = tanh2(mul2(pk2(tw.x,tw.x), tvp[i]));
                        const u64 f1 = tanh2(mul2(pk2(tw.y,tw.y), tvp[i]));
                        const u64 f2 = tanh2(mul2(pk2(tw.z,tw.z), tvp[i]));
                        const u64 f3 = tanh2(mul2(pk2(tw.w,tw.w), tvp[i]));
                        ulonglong2 oA, oB;
                        oA.x = fma2(mul2(f0, zz[4*i+0]), sub2(u0, hA.x), hA.x);
                        oA.y = fma2(mul2(f1, zz[4*i+1]), sub2(u1, hA.y), hA.y);
                        oB.x = fma2(mul2(f2, zz[4*i+2]), sub2(u2, hB.x), hB.x);
                        oB.y = fma2(mul2(f3, zz[4*i+3]), sub2(u3, hB.y), hB.y);
                        *(ulonglong2*)&sm[OFF_HT + p * HSTR + 2 * n0c]     = oA;
                        *(ulonglong2*)&sm[OFF_HT + p * HSTR + 2 * n0c + 4] = oB;
                        if (l == 1) {
                            float l0,h0,l1,h1,l2,h2,l3,h3;
                            up2(oA.x, l0, h0); up2(oA.y, l1, h1);
                            up2(oB.x, l2, h2); up2(oB.y, l3, h3);
                            const size_t rg = row0 + 2 * p;
                            *(float4*)&hids[(rg * T_STEPS + ti) * (size_t)HH + n0c]       = make_float4(l0, l1, l2, l3);
                            *(float4*)&hids[((rg + 1) * T_STEPS + ti) * (size_t)HH + n0c] = make_float4(h0, h1, h2, h3);
                        }
                    }
                }
            }
        }

        // =================== GRU (full-K split-N; all 16 warps) ===================
        u64 g_r[4], g_z[4], g_in[4], g_hn[4];
        {
            const float br0 = sm[OFF_BIH + n0s] + sm[OFF_BHH + n0s];
            const float br1 = sm[OFF_BIH + n0s + 64] + sm[OFF_BHH + n0s + 64];
            const float bz0 = sm[OFF_BIH + 128 + n0s] + sm[OFF_BHH + 128 + n0s];
            const float bz1 = sm[OFF_BIH + 128 + n0s + 64] + sm[OFF_BHH + 128 + n0s + 64];
            const float bi0 = sm[OFF_BIH + 256 + n0s],      bi1 = sm[OFF_BIH + 256 + n0s + 64];
            const float bn0 = sm[OFF_BHH + 256 + n0s],      bn1 = sm[OFF_BHH + 256 + n0s + 64];
#pragma unroll
            for (int i = 0; i < 2; i++) {
                g_r[2*i+0] = pk2(br0, br0); g_r[2*i+1] = pk2(br1, br1);
                g_z[2*i+0] = pk2(bz0, bz0); g_z[2*i+1] = pk2(bz1, bz1);
                g_in[2*i+0] = pk2(bi0, bi0); g_in[2*i+1] = pk2(bi1, bi1);
                g_hn[2*i+0] = pk2(bn0, bn0); g_hn[2*i+1] = pk2(bn1, bn1);
            }
        }
        // ghr (phase 6, slot 0)
        CP_WAIT0(); __syncthreads();
        stage_matrix(7, sm, tid, fWr, fWz, fWh, Whh, Wih); CP_COMMIT();
        pass_gh(sm + 0 * SLOT, htb, n0s, g_r);
        // ghz (phase 7, slot 1)
        CP_WAIT0(); __syncthreads();
        stage_matrix(8, sm, tid, fWr, fWz, fWh, Whh, Wih); CP_COMMIT();
        pass_gh(sm + 1 * SLOT, htb, n0s, g_z);
        // ghn (phase 8, slot 0)
        CP_WAIT0(); __syncthreads();
        stage_matrix(9, sm, tid, fWr, fWz, fWh, Whh, Wih); CP_COMMIT();
        pass_gh(sm + 0 * SLOT, htb, n0s, g_hn);
        // gi (phase 9, slot 1) + combine
        CP_WAIT0(); __syncthreads();
        stage_matrix(0, sm, tid, fWr, fWz, fWh, Whh, Wih); CP_COMMIT();   // next step Wr0
        {
            const float* sW = sm + 1 * SLOT;
            pass_gi(sW,            xtb, n0s, g_r);
            pass_gi(sW + 128 * 44, xtb, n0s, g_z);
            pass_gi(sW + 256 * 44, xtb, n0s, g_in);
#pragma unroll
            for (int i = 0; i < 2; i++) {
                const int p = pg + 8 * i;
#pragma unroll
                for (int c = 0; c < 2; c++) {
                    const int n = n0s + 64 * c;
                    float rx, ry, zx, zy;
                    up2(g_r[2*i+c], rx, ry); up2(g_z[2*i+c], zx, zy);
                    const u64 r2 = pk2(siga(rx), siga(ry));
                    const u64 z2 = pk2(siga(zx), siga(zy));
                    const u64 nn2 = tanh2(fma2(r2, g_hn[2*i+c], g_in[2*i+c]));
                    const u64 h2 = *(const u64*)&sm[OFF_HT + p * HSTR + 2 * n];
                    const u64 hn2 = fma2(z2, sub2(h2, nn2), nn2);
                    *(u64*)&sm[OFF_HT + p * HSTR + 2 * n] = hn2;
                }
            }
        }
        __syncthreads();   // h_new visible for decoder

        // =================== decoder (lo half only) ===================
        if (tid < 256) {
            const int d = tid & 31, grp = tid >> 5;   // 8 grps x 2 pairs
            const float db = sm[OFF_DB + d];
            u64 o0 = pk2(db, db), o1 = pk2(db, db);
            const float* xa0 = sm + OFF_HT + (2 * grp) * HSTR;
            const float* xa1 = xa0 + HSTR;
#pragma unroll 2
            for (int k = 0; k < 128; k += 4) {
                const float4 wv = *(const float4*)&sm[OFF_DEC + d * 132 + k];
                const u64 wa = pk2(wv.x, wv.x), wb = pk2(wv.y, wv.y);
                const u64 wc = pk2(wv.z, wv.z), wd = pk2(wv.w, wv.w);
                u64 x0, x1, x2, x3;
                LDX2(x0, x1, xa0 + k * 2);
                LDX2(x2, x3, xa0 + k * 2 + 4);
                o0 = fma2(x0, wa, o0); o0 = fma2(x1, wb, o0);
                o0 = fma2(x2, wc, o0); o0 = fma2(x3, wd, o0);
                LDX2(x0, x1, xa1 + k * 2);
                LDX2(x2, x3, xa1 + k * 2 + 4);
                o1 = fma2(x0, wa, o1); o1 = fma2(x1, wb, o1);
                o1 = fma2(x2, wc, o1); o1 = fma2(x3, wd, o1);
            }
            float v0, v1, v2, v3;
            up2(o0, v0, v1); up2(o1, v2, v3);
            const size_t r0g = row0 + 4 * grp;
            outs[((r0g + 0) * T_STEPS + ti) * (size_t)DS + d] = v0;
            outs[((r0g + 1) * T_STEPS + ti) * (size_t)DS + d] = v1;
            outs[((r0g + 2) * T_STEPS + ti) * (size_t)DS + d] = v2;
            outs[((r0g + 3) * T_STEPS + ti) * (size_t)DS + d] = v3;
        }
    }
}

extern "C" void kernel_launch(void* const* d_in, const int* in_sizes, int n_in,
                              void* d_out, int out_size)
{
    const float* s    = (const float*)d_in[0];
    const float* a    = (const float*)d_in[1];
    const float* t    = (const float*)d_in[2];
    const float* fWr  = (const float*)d_in[3];
    const float* fbr  = (const float*)d_in[4];
    const float* fWz  = (const float*)d_in[5];
    const float* fbz  = (const float*)d_in[6];
    const float* fWh  = (const float*)d_in[7];
    const float* fbh  = (const float*)d_in[8];
    const float* ftw  = (const float*)d_in[9];
    const float* Wih  = (const float*)d_in[10];
    const float* Whh  = (const float*)d_in[11];
    const float* bih  = (const float*)d_in[12];
    const float* bhh  = (const float*)d_in[13];
    const float* decW = (const float*)d_in[14];
    const float* decb = (const float*)d_in[15];

    float* outs = (float*)d_out;
    float* hids = outs + (size_t)4096 * T_STEPS * DS;

    const int SMEM = SMEM_FL * 4;
    cudaFuncSetAttribute(odernn_persistent, cudaFuncAttributeMaxDynamicSharedMemorySize, SMEM);
    odernn_persistent<<<128, NTHR, SMEM>>>(s, a, t, fWr, fbr, fWz, fbz, fWh, fbh, ftw,
                                           Wih, Whh, bih, bhh, decW, decb, outs, hids);
}

// round 12
// speedup vs baseline: 1.9966x; 1.9966x over previous
#include <cuda_runtime.h>
#include <cuda_bf16.h>
#include <stdint.h>
#include <stddef.h>

#define T_STEPS 200
#define NTHR 256

// ---------------- smem layout (byte offsets) ----------------
#define A0B    0          // weight image slot 0 (69632 B: hi plane 34816 + lo plane)
#define A1B    69632      // slot 1
#define XHhiB  139264     // h   B-tile hi [32][136] bf16 (8704 B)
#define XHloB  147968
#define XRhiB  156672     // r*h B-tile
#define XRloB  165376
#define XGhiB  174080     // gru x B-tile [32][56] bf16 (3584 B)
#define XGloB  177664
// ---- float offsets ----
#define HMf    45312      // h fp32 master [32][132]  (4224 f)
#define DECf   49536      // dec weights [k=128][33]  (4224 f)
#define FBf    53760      // flow biases [l*512 + gate*128 + n] (1024 f)
#define WTf    54784      // flow t-row weights [l*384 + gate*128 + n] (768 f)
#define GBf    55552      // gru biases: br,bz,bin,bhn (512 f)
#define DBf    56064      // dec bias (32 f)
#define TVf    56096      // t values (32 f)
#define SMEM_BYTES 224512

// weight images in gmem (built once by prep_kernel)
__device__ __align__(16) unsigned short g_wimg[356352];   // 712704 B

__constant__ int c_stageImg[12] = {1,2,3,4,5,6,9,7,10,8,11,0};
__constant__ int c_imgOff[12]   = {0,69632,139264,208896,278528,348160,
                                   417792,487424,557056,626688,655360,684032};
__constant__ int c_imgSz[12]    = {69632,69632,69632,69632,69632,69632,
                                   69632,69632,69632,28672,28672,28672};

__device__ __forceinline__ float tanha(float x) {
    float y; asm("tanh.approx.f32 %0,%1;" : "=f"(y) : "f"(x)); return y;
}
__device__ __forceinline__ float siga(float x) { return fmaf(0.5f, tanha(0.5f * x), 0.5f); }

__device__ __forceinline__ void cpa16c(char* dst, const char* src) {
    unsigned d = (unsigned)__cvta_generic_to_shared(dst);
    asm volatile("cp.async.cg.shared.global [%0], [%1], 16;" :: "r"(d), "l"(src));
}
#define CP_COMMIT() asm volatile("cp.async.commit_group;" ::: "memory")
#define CP_WAIT0()  asm volatile("cp.async.wait_group 0;" ::: "memory")

__device__ __forceinline__ void ldm4(uint32_t& r0, uint32_t& r1, uint32_t& r2, uint32_t& r3, uint32_t a) {
    asm volatile("ldmatrix.sync.aligned.m8n8.x4.shared.b16 {%0,%1,%2,%3},[%4];"
        : "=r"(r0), "=r"(r1), "=r"(r2), "=r"(r3) : "r"(a));
}
__device__ __forceinline__ void ldm2(uint32_t& r0, uint32_t& r1, uint32_t a) {
    asm volatile("ldmatrix.sync.aligned.m8n8.x2.shared.b16 {%0,%1},[%2];"
        : "=r"(r0), "=r"(r1) : "r"(a));
}
__device__ __forceinline__ void mmabf(float* d, uint32_t a0, uint32_t a1, uint32_t a2, uint32_t a3,
                                      uint32_t b0, uint32_t b1) {
    asm volatile("mma.sync.aligned.m16n8k16.row.col.f32.bf16.bf16.f32 "
        "{%0,%1,%2,%3},{%4,%5,%6,%7},{%8,%9},{%0,%1,%2,%3};"
        : "+f"(d[0]), "+f"(d[1]), "+f"(d[2]), "+f"(d[3])
        : "r"(a0), "r"(a1), "r"(a2), "r"(a3), "r"(b0), "r"(b1));
}

// hi/lo bf16 store helpers (strides 136 / 56 elems)
__device__ __forceinline__ void st_hl(char* smc, int hiB, int loB, int b, int k, float v) {
    __nv_bfloat16 h = __float2bfloat16(v);
    __nv_bfloat16 l = __float2bfloat16(v - __bfloat162float(h));
    const int e = (b * 136 + k) * 2;
    *(__nv_bfloat16*)(smc + hiB + e) = h;
    *(__nv_bfloat16*)(smc + loB + e) = l;
}
__device__ __forceinline__ void st_hl56(char* smc, int hiB, int loB, int b, int k, float v) {
    __nv_bfloat16 h = __float2bfloat16(v);
    __nv_bfloat16 l = __float2bfloat16(v - __bfloat162float(h));
    const int e = (b * 56 + k) * 2;
    *(__nv_bfloat16*)(smc + hiB + e) = h;
    *(__nv_bfloat16*)(smc + loB + e) = l;
}

// one matvec pass: acc[16] += (Ahi+Alo)(Bhi+Blo) [3-product]
// Aaddr = sb + slot + lane A offset; Bhi/Blo = sb + plane + lane B offset
__device__ __forceinline__ void mma_pass(uint32_t Aaddr, int planeA,
                                         uint32_t Bhi, uint32_t Blo,
                                         int strideX, int ksteps, float acc[16])
{
#pragma unroll 1
    for (int ks = 0; ks < ksteps; ks++) {
        uint32_t ah0, ah1, ah2, ah3, al0, al1, al2, al3;
        const uint32_t ab = Aaddr + ks * 32;
        ldm4(ah0, ah1, ah2, ah3, ab);
        ldm4(al0, al1, al2, al3, ab + planeA);
#pragma unroll
        for (int nt = 0; nt < 4; nt++) {
            uint32_t bh0, bh1, bl0, bl1;
            const uint32_t bb = ks * 32 + nt * 8 * strideX;
            ldm2(bh0, bh1, Bhi + bb);
            ldm2(bl0, bl1, Blo + bb);
            mmabf(acc + 4 * nt, ah0, ah1, ah2, ah3, bh0, bh1);
            mmabf(acc + 4 * nt, ah0, ah1, ah2, ah3, bl0, bl1);
            mmabf(acc + 4 * nt, al0, al1, al2, al3, bh0, bh1);
        }
    }
}

// -------------------- prep: build bf16 hi/lo weight images --------------------
__global__ void prep_kernel(const float* fWr, const float* fWz, const float* fWh,
                            const float* Whh, const float* Wih)
{
    const int img = blockIdx.x, tid = threadIdx.x;
    if (img < 9) {
        unsigned short* dst = g_wimg + img * 34816;        // hi plane; lo at +17408
        for (int i = tid; i < 128 * 136; i += 256) {
            const int n = i / 136, k = i - n * 136;
            float v = 0.0f;
            if (k < 128) {
                if (img < 6) {
                    const int l = img / 3, g = img % 3;
                    const float* W = (g == 0 ? fWr : (g == 1 ? fWz : fWh)) + (size_t)l * 129 * 128;
                    v = W[k * 128 + n];
                } else {
                    v = Whh[(size_t)(img - 6) * 16384 + n * 128 + k];
                }
            }
            __nv_bfloat16 h = __float2bfloat16(v);
            __nv_bfloat16 l = __float2bfloat16(v - __bfloat162float(h));
            dst[n * 136 + k]         = *reinterpret_cast<unsigned short*>(&h);
            dst[17408 + n * 136 + k] = *reinterpret_cast<unsigned short*>(&l);
        }
    } else {
        const int g = img - 9;
        unsigned short* dst = g_wimg + 313344 + g * 14336; // hi plane; lo at +7168
        for (int i = tid; i < 128 * 56; i += 256) {
            const int n = i / 56, k = i - n * 56;
            const float v = (k < 40) ? Wih[(size_t)(g * 128 + n) * 40 + k] : 0.0f;
            __nv_bfloat16 h = __float2bfloat16(v);
            __nv_bfloat16 l = __float2bfloat16(v - __bfloat162float(h));
            dst[n * 56 + k]        = *reinterpret_cast<unsigned short*>(&h);
            dst[7168 + n * 56 + k] = *reinterpret_cast<unsigned short*>(&l);
        }
    }
}

__device__ __forceinline__ void phsync(int p, char* smc, int tid) {
    CP_WAIT0(); __syncthreads();
    const int img = c_stageImg[p];
    char* dst = smc + ((p & 1) ? A0B : A1B);
    const char* src = (const char*)g_wimg + c_imgOff[img];
    const int n = c_imgSz[img] >> 4;
    for (int i = tid; i < n; i += NTHR) cpa16c(dst + i * 16, src + i * 16);
    CP_COMMIT();
}

#define ZACC() do { _Pragma("unroll") for (int q = 0; q < 16; q++) acc[q] = 0.0f; } while (0)
#define CURS(p) (sb + (((p) & 1) ? A1B : A0B))

__global__ void __launch_bounds__(NTHR, 1)
odernn_mma(const float* __restrict__ s, const float* __restrict__ a, const float* __restrict__ t,
           const float* __restrict__ fWr, const float* __restrict__ fbr,
           const float* __restrict__ fWz, const float* __restrict__ fbz,
           const float* __restrict__ fWh, const float* __restrict__ fbh,
           const float* __restrict__ ftw,
           const float* __restrict__ bih, const float* __restrict__ bhh,
           const float* __restrict__ decW, const float* __restrict__ decb,
           float* __restrict__ outs, float* __restrict__ hids)
{
    extern __shared__ char smc[];
    float* smf = (float*)smc;
    const int tid = threadIdx.x;
    const int row0 = blockIdx.x * 32;
    const uint32_t sb = (uint32_t)__cvta_generic_to_shared(smc);

    const int w = tid >> 5, lane = tid & 31;
    const int g = lane >> 2, tg = lane & 3;
    const int og = 16 * w + g, og8 = og + 8;
    // ldmatrix lane offsets
    const int arow = (lane & 7) + ((lane >> 3) & 1) * 8;
    const int acolh = (lane >> 4) * 16;
    const uint32_t aoffB = (uint32_t)((16 * w + arow) * 272 + acolh);
    const uint32_t aoffG = (uint32_t)((16 * w + arow) * 112 + acolh);
    const uint32_t boffB = (uint32_t)((lane & 7) * 272 + ((lane >> 3) & 1) * 16);
    const uint32_t boffG = (uint32_t)((lane & 7) * 112 + ((lane >> 3) & 1) * 16);

    // ---- one-time init ----
    for (int i = tid; i < 10496; i += NTHR) smf[34816 + i] = 0.0f;   // XH/XR/XG hi+lo zero
    for (int i = tid; i < 4224; i += NTHR) smf[HMf + i] = 0.0f;      // h master zero
    for (int i = tid; i < 4096; i += NTHR) {                          // dec [k][33]
        const int d = i >> 7, k = i & 127;
        smf[DECf + k * 33 + d] = decW[i];
    }
    if (tid < 128) {
#pragma unroll
        for (int l = 0; l < 2; l++) {
            smf[FBf + l * 512 +   0 + tid] = fbr[l * 128 + tid];
            smf[FBf + l * 512 + 128 + tid] = fbz[l * 128 + tid];
            smf[FBf + l * 512 + 256 + tid] = fbh[l * 128 + tid];
            smf[FBf + l * 512 + 384 + tid] = ftw[l * 128 + tid];
            smf[WTf + l * 384 +   0 + tid] = fWr[l * 16512 + 16384 + tid];
            smf[WTf + l * 384 + 128 + tid] = fWz[l * 16512 + 16384 + tid];
            smf[WTf + l * 384 + 256 + tid] = fWh[l * 16512 + 16384 + tid];
        }
        smf[GBf +   0 + tid] = bih[tid] + bhh[tid];
        smf[GBf + 128 + tid] = bih[128 + tid] + bhh[128 + tid];
        smf[GBf + 256 + tid] = bih[256 + tid];
        smf[GBf + 384 + tid] = bhh[256 + tid];
    }
    if (tid < 32) smf[DBf + tid] = decb[tid];
    __syncthreads();

    // prologue: stage img0 -> slot0
    {
        const char* src = (const char*)g_wimg;
        for (int i = tid; i < (69632 >> 4); i += NTHR) cpa16c(smc + A0B + i * 16, src + i * 16);
        CP_COMMIT();
    }

#pragma unroll 1
    for (int ti = 0; ti < T_STEPS; ti++) {
        if (tid < 32) smf[TVf + tid] = t[(size_t)(row0 + tid) * T_STEPS + ti];
        for (int i = tid; i < 1280; i += NTHR) {
            const int b = i / 40, c = i - b * 40;
            const float v = (c < 32) ? s[((size_t)(row0 + b) * T_STEPS + ti) * 32 + c]
                                     : a[((size_t)(row0 + b) * T_STEPS + ti) * 8 + (c - 32)];
            st_hl56(smc, XGhiB, XGloB, b, c, v);
        }

        float acc[16], zf[16], rv[16];

        // =================== flow layers ===================
#pragma unroll 1
        for (int l = 0; l < 2; l++) {
            const int pb = l * 3;

            // ---- pass r ----
            phsync(pb + 0, smc, tid);
            ZACC();
            mma_pass(CURS(pb + 0) + aoffB, 34816, sb + XHhiB + boffB, sb + XHloB + boffB, 272, 8, acc);
            {
                const float wtA = smf[WTf + l * 384 + og],  wtB = smf[WTf + l * 384 + og8];
                const float brA = smf[FBf + l * 512 + og],  brB = smf[FBf + l * 512 + og8];
#pragma unroll
                for (int nt = 0; nt < 4; nt++) {
                    const int b0 = 8 * nt + 2 * tg;
                    const float tv0 = smf[TVf + b0], tv1 = smf[TVf + b0 + 1];
                    float r0 = 0.8f * siga(acc[4 * nt + 0] + wtA * tv0 + brA);
                    float r1 = 0.8f * siga(acc[4 * nt + 1] + wtA * tv1 + brA);
                    float r2 = 0.8f * siga(acc[4 * nt + 2] + wtB * tv0 + brB);
                    float r3 = 0.8f * siga(acc[4 * nt + 3] + wtB * tv1 + brB);
                    st_hl(smc, XRhiB, XRloB, b0,     og,  r0 * smf[HMf + b0 * 132 + og]);
                    st_hl(smc, XRhiB, XRloB, b0 + 1, og,  r1 * smf[HMf + (b0 + 1) * 132 + og]);
                    st_hl(smc, XRhiB, XRloB, b0,     og8, r2 * smf[HMf + b0 * 132 + og8]);
                    st_hl(smc, XRhiB, XRloB, b0 + 1, og8, r3 * smf[HMf + (b0 + 1) * 132 + og8]);
                }
            }

            // ---- pass z ----
            phsync(pb + 1, smc, tid);
            ZACC();
            mma_pass(CURS(pb + 1) + aoffB, 34816, sb + XHhiB + boffB, sb + XHloB + boffB, 272, 8, acc);
            {
                const float wtA = smf[WTf + l * 384 + 128 + og],  wtB = smf[WTf + l * 384 + 128 + og8];
                const float bzA = smf[FBf + l * 512 + 128 + og],  bzB = smf[FBf + l * 512 + 128 + og8];
#pragma unroll
                for (int nt = 0; nt < 4; nt++) {
                    const int b0 = 8 * nt + 2 * tg;
                    const float tv0 = smf[TVf + b0], tv1 = smf[TVf + b0 + 1];
                    zf[4 * nt + 0] = 0.4f * siga(acc[4 * nt + 0] + wtA * tv0 + bzA);
                    zf[4 * nt + 1] = 0.4f * siga(acc[4 * nt + 1] + wtA * tv1 + bzA);
                    zf[4 * nt + 2] = 0.4f * siga(acc[4 * nt + 2] + wtB * tv0 + bzB);
                    zf[4 * nt + 3] = 0.4f * siga(acc[4 * nt + 3] + wtB * tv1 + bzB);
                }
            }

            // ---- pass u + combine ----
            phsync(pb + 2, smc, tid);
            ZACC();
            mma_pass(CURS(pb + 2) + aoffB, 34816, sb + XRhiB + boffB, sb + XRloB + boffB, 272, 8, acc);
            {
                const float wtA = smf[WTf + l * 384 + 256 + og],  wtB = smf[WTf + l * 384 + 256 + og8];
                const float bhA = smf[FBf + l * 512 + 256 + og],  bhB = smf[FBf + l * 512 + 256 + og8];
                const float twA = smf[FBf + l * 512 + 384 + og],  twB = smf[FBf + l * 512 + 384 + og8];
#define FLOWU(j, bb, oo, wt, bh, tw, tvv) do { \
                    const float u_ = tanha(acc[j] + (wt) * (tvv) + (bh)); \
                    const float phi_ = tanha((tw) * (tvv)); \
                    const float h_ = smf[HMf + (bb) * 132 + (oo)]; \
                    const float hn_ = h_ + phi_ * zf[j] * (u_ - h_); \
                    smf[HMf + (bb) * 132 + (oo)] = hn_; \
                    st_hl(smc, XHhiB, XHloB, (bb), (oo), hn_); \
                    if (l == 1) hids[((size_t)(row0 + (bb)) * T_STEPS + ti) * 128 + (oo)] = hn_; \
                } while (0)
#pragma unroll
                for (int nt = 0; nt < 4; nt++) {
                    const int b0 = 8 * nt + 2 * tg;
                    const float tv0 = smf[TVf + b0], tv1 = smf[TVf + b0 + 1];
                    FLOWU(4 * nt + 0, b0,     og,  wtA, bhA, twA, tv0);
                    FLOWU(4 * nt + 1, b0 + 1, og,  wtA, bhA, twA, tv1);
                    FLOWU(4 * nt + 2, b0,     og8, wtB, bhB, twB, tv0);
                    FLOWU(4 * nt + 3, b0 + 1, og8, wtB, bhB, twB, tv1);
                }
#undef FLOWU
            }
        }

        // =================== GRU ===================
        // r gate: gh_r then += gi_r
        phsync(6, smc, tid);
        ZACC();
        mma_pass(CURS(6) + aoffB, 34816, sb + XHhiB + boffB, sb + XHloB + boffB, 272, 8, acc);
        phsync(7, smc, tid);
        mma_pass(CURS(7) + aoffG, 14336, sb + XGhiB + boffG, sb + XGloB + boffG, 112, 3, acc);
        {
            const float bA = smf[GBf + og], bB = smf[GBf + og8];
#pragma unroll
            for (int nt = 0; nt < 4; nt++) {
                rv[4 * nt + 0] = siga(acc[4 * nt + 0] + bA);
                rv[4 * nt + 1] = siga(acc[4 * nt + 1] + bA);
                rv[4 * nt + 2] = siga(acc[4 * nt + 2] + bB);
                rv[4 * nt + 3] = siga(acc[4 * nt + 3] + bB);
            }
        }
        // z gate
        phsync(8, smc, tid);
        ZACC();
        mma_pass(CURS(8) + aoffB, 34816, sb + XHhiB + boffB, sb + XHloB + boffB, 272, 8, acc);
        phsync(9, smc, tid);
        mma_pass(CURS(9) + aoffG, 14336, sb + XGhiB + boffG, sb + XGloB + boffG, 112, 3, acc);
        {
            const float bA = smf[GBf + 128 + og], bB = smf[GBf + 128 + og8];
#pragma unroll
            for (int nt = 0; nt < 4; nt++) {
                zf[4 * nt + 0] = siga(acc[4 * nt + 0] + bA);
                zf[4 * nt + 1] = siga(acc[4 * nt + 1] + bA);
                zf[4 * nt + 2] = siga(acc[4 * nt + 2] + bB);
                zf[4 * nt + 3] = siga(acc[4 * nt + 3] + bB);
            }
        }
        // gh_n -> fold into rv
        phsync(10, smc, tid);
        ZACC();
        mma_pass(CURS(10) + aoffB, 34816, sb + XHhiB + boffB, sb + XHloB + boffB, 272, 8, acc);
        {
            const float bA = smf[GBf + 384 + og], bB = smf[GBf + 384 + og8];
#pragma unroll
            for (int nt = 0; nt < 4; nt++) {
                rv[4 * nt + 0] *= (acc[4 * nt + 0] + bA);
                rv[4 * nt + 1] *= (acc[4 * nt + 1] + bA);
                rv[4 * nt + 2] *= (acc[4 * nt + 2] + bB);
                rv[4 * nt + 3] *= (acc[4 * nt + 3] + bB);
            }
        }
        // gi_n + combine
        phsync(11, smc, tid);
        ZACC();
        mma_pass(CURS(11) + aoffG, 14336, sb + XGhiB + boffG, sb + XGloB + boffG, 112, 3, acc);
        {
            const float bA = smf[GBf + 256 + og], bB = smf[GBf + 256 + og8];
#define GRUF(j, bb, oo, bi) do { \
                const float nn_ = tanha(acc[j] + (bi) + rv[j]); \
                const float h_ = smf[HMf + (bb) * 132 + (oo)]; \
                const float hn_ = nn_ + zf[j] * (h_ - nn_); \
                smf[HMf + (bb) * 132 + (oo)] = hn_; \
                st_hl(smc, XHhiB, XHloB, (bb), (oo), hn_); \
            } while (0)
#pragma unroll
            for (int nt = 0; nt < 4; nt++) {
                const int b0 = 8 * nt + 2 * tg;
                GRUF(4 * nt + 0, b0,     og,  bA);
                GRUF(4 * nt + 1, b0 + 1, og,  bA);
                GRUF(4 * nt + 2, b0,     og8, bB);
                GRUF(4 * nt + 3, b0 + 1, og8, bB);
            }
#undef GRUF
        }
        __syncthreads();   // HM complete for decoder

        // =================== decoder (fp32) ===================
        {
            const int d = tid & 31;
            const int bq = (tid >> 5) * 4;
            float o0, o1, o2, o3;
            o0 = o1 = o2 = o3 = smf[DBf + d];
#pragma unroll 1
            for (int k = 0; k < 128; k += 4) {
                const float w0 = smf[DECf + (k + 0) * 33 + d];
                const float w1 = smf[DECf + (k + 1) * 33 + d];
                const float w2 = smf[DECf + (k + 2) * 33 + d];
                const float w3 = smf[DECf + (k + 3) * 33 + d];
                float4 h0 = *(const float4*)&smf[HMf + (bq + 0) * 132 + k];
                float4 h1 = *(const float4*)&smf[HMf + (bq + 1) * 132 + k];
                float4 h2 = *(const float4*)&smf[HMf + (bq + 2) * 132 + k];
                float4 h3 = *(const float4*)&smf[HMf + (bq + 3) * 132 + k];
                o0 = fmaf(h0.x, w0, fmaf(h0.y, w1, fmaf(h0.z, w2, fmaf(h0.w, w3, o0))));
                o1 = fmaf(h1.x, w0, fmaf(h1.y, w1, fmaf(h1.z, w2, fmaf(h1.w, w3, o1))));
                o2 = fmaf(h2.x, w0, fmaf(h2.y, w1, fmaf(h2.z, w2, fmaf(h2.w, w3, o2))));
                o3 = fmaf(h3.x, w0, fmaf(h3.y, w1, fmaf(h3.z, w2, fmaf(h3.w, w3, o3))));
            }
            outs[((size_t)(row0 + bq + 0) * T_STEPS + ti) * 32 + d] = o0;
            outs[((size_t)(row0 + bq + 1) * T_STEPS + ti) * 32 + d] = o1;
            outs[((size_t)(row0 + bq + 2) * T_STEPS + ti) * 32 + d] = o2;
            outs[((size_t)(row0 + bq + 3) * T_STEPS + ti) * 32 + d] = o3;
        }
    }
}

extern "C" void kernel_launch(void* const* d_in, const int* in_sizes, int n_in,
                              void* d_out, int out_size)
{
    (void)in_sizes; (void)n_in; (void)out_size;
    const float* s    = (const float*)d_in[0];
    const float* a    = (const float*)d_in[1];
    const float* t    = (const float*)d_in[2];
    const float* fWr  = (const float*)d_in[3];
    const float* fbr  = (const float*)d_in[4];
    const float* fWz  = (const float*)d_in[5];
    const float* fbz  = (const float*)d_in[6];
    const float* fWh  = (const float*)d_in[7];
    const float* fbh  = (const float*)d_in[8];
    const float* ftw  = (const float*)d_in[9];
    const float* Wih  = (const float*)d_in[10];
    const float* Whh  = (const float*)d_in[11];
    const float* bih  = (const float*)d_in[12];
    const float* bhh  = (const float*)d_in[13];
    const float* decW = (const float*)d_in[14];
    const float* decb = (const float*)d_in[15];

    float* outs = (float*)d_out;
    float* hids = outs + (size_t)4096 * T_STEPS * 32;

    prep_kernel<<<12, 256>>>(fWr, fWz, fWh, Whh, Wih);

    cudaFuncSetAttribute(odernn_mma, cudaFuncAttributeMaxDynamicSharedMemorySize, SMEM_BYTES);
    odernn_mma<<<128, NTHR, SMEM_BYTES>>>(s, a, t, fWr, fbr, fWz, fbz, fWh, fbh, ftw,
                                          bih, bhh, decW, decb, outs, hids);
}